// round 2
// baseline (speedup 1.0000x reference)
#include <cuda_runtime.h>
#include <math.h>

#define NN 50000
#define EE 800000
#define ET (EE + NN)
#define GG 64
#define F_IN 128
#define H1DIM 256   // HEADS * HID
#define HEADS 4
#define HID 64
#define H2DIM 32
#define NEG_SLOPE 0.2f

// ---------------- scratch (device globals; no allocation allowed) ----------------
__device__ __align__(16) float g_h1[NN * H1DIM];    // layer1 transformed features
__device__ __align__(16) float g_out1[NN * H1DIM];  // layer1 aggregation output
__device__ __align__(16) float g_as1[NN * 4];
__device__ __align__(16) float g_ad1[NN * 4];
__device__ __align__(16) float g_m1[NN * 4];
__device__ __align__(16) float g_den1[NN * 4];
__device__ __align__(16) float g_ex1[ET * 4];
__device__ __align__(16) float g_h2[NN * H2DIM];
__device__ __align__(16) float g_out2[NN * H2DIM];
__device__ float g_as2[NN];
__device__ float g_ad2[NN];
__device__ float g_m2[NN];
__device__ float g_den2[NN];
__device__ float g_ex2[ET];
__device__ float g_pool[GG * H2DIM];
__device__ float g_cnt[GG];

// ---------------- helpers ----------------
__device__ __forceinline__ void atomicMaxF(float* addr, float val) {
    int bits = __float_as_int(val);
    if (bits >= 0) {
        atomicMax((int*)addr, bits);
    } else {
        atomicMin((unsigned int*)addr, (unsigned int)bits);
    }
}

__device__ __forceinline__ void red_add_v4(float* addr, float4 v) {
    asm volatile("red.global.add.v4.f32 [%0], {%1,%2,%3,%4};"
                 :: "l"(addr), "f"(v.x), "f"(v.y), "f"(v.z), "f"(v.w)
                 : "memory");
}

__device__ __forceinline__ float leaky(float e) {
    return (e >= 0.f) ? e : NEG_SLOPE * e;
}

__device__ __forceinline__ void edge_src_dst(const int* adj, int e, int& src, int& dst) {
    if (e < EE) {
        src = adj[e];
        dst = adj[EE + e];
    } else {
        src = dst = e - EE;
    }
}

// ---------------- init ----------------
__global__ void init_kernel() {
    int stride = gridDim.x * blockDim.x;
    int i0 = blockIdx.x * blockDim.x + threadIdx.x;
    for (int j = i0; j < NN * H1DIM; j += stride) g_out1[j] = 0.f;
    for (int j = i0; j < NN * H2DIM; j += stride) g_out2[j] = 0.f;
    for (int j = i0; j < NN * 4; j += stride) { g_den1[j] = 0.f; g_m1[j] = -INFINITY; }
    for (int j = i0; j < NN; j += stride)     { g_den2[j] = 0.f; g_m2[j] = -INFINITY; }
    for (int j = i0; j < GG * H2DIM; j += stride) g_pool[j] = 0.f;
    for (int j = i0; j < GG; j += stride) g_cnt[j] = 0.f;
}

// ---------------- GEMM1: h1 = x @ W1  (NNx128 @ 128x256) ----------------
// block: 256 threads, 8 rows per block, thread col = tid
__global__ void gemm1_kernel(const float* __restrict__ x, const float* __restrict__ W1) {
    __shared__ float xs[8][F_IN];
    int row0 = blockIdx.x * 8;
    int tid = threadIdx.x;
    for (int i = tid; i < 8 * F_IN; i += 256) {
        int r = i >> 7, c = i & 127;
        xs[r][c] = x[(row0 + r) * F_IN + c];
    }
    __syncthreads();
    float acc[8];
#pragma unroll
    for (int r = 0; r < 8; r++) acc[r] = 0.f;
    int col = tid;
#pragma unroll 4
    for (int k = 0; k < F_IN; k++) {
        float w = W1[k * H1DIM + col];
#pragma unroll
        for (int r = 0; r < 8; r++) acc[r] += xs[r][k] * w;
    }
#pragma unroll
    for (int r = 0; r < 8; r++) g_h1[(row0 + r) * H1DIM + col] = acc[r];
}

// ---------------- alpha1: per-node per-head dot products ----------------
// warp per node; lane L handles elements [8L, 8L+8); lanes 8k..8k+7 cover head k
__global__ void alpha1_kernel(const float* __restrict__ a_src, const float* __restrict__ a_dst) {
    int warp = (blockIdx.x * blockDim.x + threadIdx.x) >> 5;
    int lane = threadIdx.x & 31;
    if (warp >= NN) return;
    const float4* hrow = (const float4*)&g_h1[warp * H1DIM];
    float4 h0 = hrow[lane * 2], h1v = hrow[lane * 2 + 1];
    float4 s0 = ((const float4*)a_src)[lane * 2], s1 = ((const float4*)a_src)[lane * 2 + 1];
    float4 d0 = ((const float4*)a_dst)[lane * 2], d1 = ((const float4*)a_dst)[lane * 2 + 1];
    float ps = h0.x*s0.x + h0.y*s0.y + h0.z*s0.z + h0.w*s0.w
             + h1v.x*s1.x + h1v.y*s1.y + h1v.z*s1.z + h1v.w*s1.w;
    float pd = h0.x*d0.x + h0.y*d0.y + h0.z*d0.z + h0.w*d0.w
             + h1v.x*d1.x + h1v.y*d1.y + h1v.z*d1.z + h1v.w*d1.w;
#pragma unroll
    for (int off = 4; off; off >>= 1) {
        ps += __shfl_down_sync(0xffffffffu, ps, off);
        pd += __shfl_down_sync(0xffffffffu, pd, off);
    }
    if ((lane & 7) == 0) {
        g_as1[warp * 4 + (lane >> 3)] = ps;
        g_ad1[warp * 4 + (lane >> 3)] = pd;
    }
}

// ---------------- edge pass 1 (layer1): e + leaky + segment max ----------------
__global__ void edge1_max_kernel(const int* __restrict__ adj) {
    int e = blockIdx.x * blockDim.x + threadIdx.x;
    if (e >= ET) return;
    int src, dst; edge_src_dst(adj, e, src, dst);
    float4 as = *(const float4*)&g_as1[src * 4];
    float4 ad = *(const float4*)&g_ad1[dst * 4];
    float4 ev;
    ev.x = leaky(as.x + ad.x);
    ev.y = leaky(as.y + ad.y);
    ev.z = leaky(as.z + ad.z);
    ev.w = leaky(as.w + ad.w);
    *(float4*)&g_ex1[e * 4] = ev;
    atomicMaxF(&g_m1[dst * 4 + 0], ev.x);
    atomicMaxF(&g_m1[dst * 4 + 1], ev.y);
    atomicMaxF(&g_m1[dst * 4 + 2], ev.z);
    atomicMaxF(&g_m1[dst * 4 + 3], ev.w);
}

// ---------------- edge pass 2 (layer1): exp + segment sum ----------------
__global__ void edge1_exp_kernel(const int* __restrict__ adj) {
    int e = blockIdx.x * blockDim.x + threadIdx.x;
    if (e >= ET) return;
    int src, dst; edge_src_dst(adj, e, src, dst);
    (void)src;
    float4 ev = *(const float4*)&g_ex1[e * 4];
    float4 m = *(const float4*)&g_m1[dst * 4];
    float4 xv;
    xv.x = expf(ev.x - m.x);
    xv.y = expf(ev.y - m.y);
    xv.z = expf(ev.z - m.z);
    xv.w = expf(ev.w - m.w);
    *(float4*)&g_ex1[e * 4] = xv;
    red_add_v4(&g_den1[dst * 4], xv);
}

// ---------------- edge pass 3 (layer1): normalize ----------------
__global__ void edge1_div_kernel(const int* __restrict__ adj) {
    int e = blockIdx.x * blockDim.x + threadIdx.x;
    if (e >= ET) return;
    int src, dst; edge_src_dst(adj, e, src, dst);
    (void)src;
    float4 xv = *(const float4*)&g_ex1[e * 4];
    float4 dn = *(const float4*)&g_den1[dst * 4];
    xv.x /= dn.x; xv.y /= dn.y; xv.z /= dn.z; xv.w /= dn.w;
    *(float4*)&g_ex1[e * 4] = xv;
}

// ---------------- edge aggregation (layer1): out1[dst] += alpha * h1[src] ----------------
// one thread per (edge, float4-chunk); 64 chunks per edge; chunk>>4 = head
__global__ void edge1_agg_kernel(const int* __restrict__ adj) {
    unsigned g = blockIdx.x * blockDim.x + threadIdx.x;
    if (g >= (unsigned)ET * 64u) return;
    int e = g >> 6;
    int c = g & 63;
    int head = c >> 4;
    int src, dst; edge_src_dst(adj, e, src, dst);
    float alpha = g_ex1[e * 4 + head];
    float4 hv = *(const float4*)&g_h1[src * H1DIM + c * 4];
    hv.x *= alpha; hv.y *= alpha; hv.z *= alpha; hv.w *= alpha;
    red_add_v4(&g_out1[dst * H1DIM + c * 4], hv);
}

// ---------------- bias + relu (in place on out1) ----------------
__global__ void bias_relu1_kernel(const float* __restrict__ b1) {
    int i = blockIdx.x * blockDim.x + threadIdx.x;  // float4 index
    if (i >= NN * (H1DIM / 4)) return;
    int c4 = i & (H1DIM / 4 - 1);
    float4 b = ((const float4*)b1)[c4];
    float4 v = ((float4*)g_out1)[i];
    v.x = fmaxf(v.x + b.x, 0.f);
    v.y = fmaxf(v.y + b.y, 0.f);
    v.z = fmaxf(v.z + b.z, 0.f);
    v.w = fmaxf(v.w + b.w, 0.f);
    ((float4*)g_out1)[i] = v;
}

// ---------------- GEMM2: h2 = out1 @ W2  (NNx256 @ 256x32) ----------------
// block: 256 threads = 8 rows x 32 cols
__global__ void gemm2_kernel(const float* __restrict__ W2) {
    __shared__ float xs[8][H1DIM];
    int row0 = blockIdx.x * 8;
    int tid = threadIdx.x;
    for (int i = tid; i < 8 * H1DIM; i += 256) {
        int r = i >> 8, c = i & 255;
        xs[r][c] = g_out1[(row0 + r) * H1DIM + c];
    }
    __syncthreads();
    int r = tid >> 5, c = tid & 31;
    float acc = 0.f;
#pragma unroll 8
    for (int k = 0; k < H1DIM; k++) acc += xs[r][k] * W2[k * H2DIM + c];
    g_h2[(row0 + r) * H2DIM + c] = acc;
}

// ---------------- alpha2: per-node dot over 32 dims (1 head) ----------------
__global__ void alpha2_kernel(const float* __restrict__ a_src, const float* __restrict__ a_dst) {
    int warp = (blockIdx.x * blockDim.x + threadIdx.x) >> 5;
    int lane = threadIdx.x & 31;
    if (warp >= NN) return;
    float h = g_h2[warp * H2DIM + lane];
    float ps = h * a_src[lane];
    float pd = h * a_dst[lane];
#pragma unroll
    for (int off = 16; off; off >>= 1) {
        ps += __shfl_down_sync(0xffffffffu, ps, off);
        pd += __shfl_down_sync(0xffffffffu, pd, off);
    }
    if (lane == 0) { g_as2[warp] = ps; g_ad2[warp] = pd; }
}

// ---------------- edge passes (layer2) ----------------
__global__ void edge2_max_kernel(const int* __restrict__ adj) {
    int e = blockIdx.x * blockDim.x + threadIdx.x;
    if (e >= ET) return;
    int src, dst; edge_src_dst(adj, e, src, dst);
    float ev = leaky(g_as2[src] + g_ad2[dst]);
    g_ex2[e] = ev;
    atomicMaxF(&g_m2[dst], ev);
}

__global__ void edge2_exp_kernel(const int* __restrict__ adj) {
    int e = blockIdx.x * blockDim.x + threadIdx.x;
    if (e >= ET) return;
    int src, dst; edge_src_dst(adj, e, src, dst);
    (void)src;
    float xv = expf(g_ex2[e] - g_m2[dst]);
    g_ex2[e] = xv;
    atomicAdd(&g_den2[dst], xv);
}

__global__ void edge2_div_kernel(const int* __restrict__ adj) {
    int e = blockIdx.x * blockDim.x + threadIdx.x;
    if (e >= ET) return;
    int src, dst; edge_src_dst(adj, e, src, dst);
    (void)src;
    g_ex2[e] = g_ex2[e] / g_den2[dst];
}

// one thread per (edge, float4-chunk); 8 chunks per edge
__global__ void edge2_agg_kernel(const int* __restrict__ adj) {
    unsigned g = blockIdx.x * blockDim.x + threadIdx.x;
    if (g >= (unsigned)ET * 8u) return;
    int e = g >> 3;
    int c = g & 7;
    int src, dst; edge_src_dst(adj, e, src, dst);
    float alpha = g_ex2[e];
    float4 hv = *(const float4*)&g_h2[src * H2DIM + c * 4];
    hv.x *= alpha; hv.y *= alpha; hv.z *= alpha; hv.w *= alpha;
    red_add_v4(&g_out2[dst * H2DIM + c * 4], hv);
}

// ---------------- bias + log_softmax + pooled segment sum ----------------
// warp per node, lane = column (32 cols)
__global__ void lsm_pool_kernel(const float* __restrict__ b2, const int* __restrict__ batch) {
    int warp = (blockIdx.x * blockDim.x + threadIdx.x) >> 5;
    int lane = threadIdx.x & 31;
    if (warp >= NN) return;
    float v = g_out2[warp * H2DIM + lane] + b2[lane];
    float mx = v;
#pragma unroll
    for (int off = 16; off; off >>= 1) mx = fmaxf(mx, __shfl_xor_sync(0xffffffffu, mx, off));
    float ex = expf(v - mx);
    float s = ex;
#pragma unroll
    for (int off = 16; off; off >>= 1) s += __shfl_xor_sync(0xffffffffu, s, off);
    float lsm = v - mx - logf(s);
    int b = batch[warp];
    atomicAdd(&g_pool[b * H2DIM + lane], lsm);
    if (lane == 0) atomicAdd(&g_cnt[b], 1.0f);
}

// ---------------- final: (pooled/count) @ lin_W + lin_b ----------------
__global__ void final_kernel(const float* __restrict__ lin_W, const float* __restrict__ lin_b,
                             float* __restrict__ out) {
    int g = threadIdx.x;
    if (g >= GG) return;
    float inv = 1.0f / fmaxf(g_cnt[g], 1.0f);
    float acc = lin_b[0];
#pragma unroll
    for (int j = 0; j < H2DIM; j++) acc += g_pool[g * H2DIM + j] * inv * lin_W[j];
    out[g] = acc;
}

// ---------------- launcher ----------------
extern "C" void kernel_launch(void* const* d_in, const int* in_sizes, int n_in,
                              void* d_out, int out_size) {
    const float* x      = (const float*)d_in[0];
    const int*   adj    = (const int*)d_in[1];
    const int*   batch  = (const int*)d_in[2];
    const float* W1     = (const float*)d_in[3];
    const float* a1_src = (const float*)d_in[4];
    const float* a1_dst = (const float*)d_in[5];
    const float* b1     = (const float*)d_in[6];
    const float* W2     = (const float*)d_in[7];
    const float* a2_src = (const float*)d_in[8];
    const float* a2_dst = (const float*)d_in[9];
    const float* b2     = (const float*)d_in[10];
    const float* lin_W  = (const float*)d_in[11];
    const float* lin_b  = (const float*)d_in[12];
    float* out = (float*)d_out;

    const int TB = 256;
    init_kernel<<<1184, TB>>>();

    gemm1_kernel<<<NN / 8, TB>>>(x, W1);
    alpha1_kernel<<<(NN * 32 + TB - 1) / TB, TB>>>(a1_src, a1_dst);

    int eb = (ET + TB - 1) / TB;
    edge1_max_kernel<<<eb, TB>>>(adj);
    edge1_exp_kernel<<<eb, TB>>>(adj);
    edge1_div_kernel<<<eb, TB>>>(adj);
    edge1_agg_kernel<<<(int)(((unsigned)ET * 64u + TB - 1) / TB), TB>>>(adj);

    bias_relu1_kernel<<<(NN * (H1DIM / 4) + TB - 1) / TB, TB>>>(b1);

    gemm2_kernel<<<NN / 8, TB>>>(W2);
    alpha2_kernel<<<(NN * 32 + TB - 1) / TB, TB>>>(a2_src, a2_dst);

    edge2_max_kernel<<<eb, TB>>>(adj);
    edge2_exp_kernel<<<eb, TB>>>(adj);
    edge2_div_kernel<<<eb, TB>>>(adj);
    edge2_agg_kernel<<<(int)(((unsigned)ET * 8u + TB - 1) / TB), TB>>>(adj);

    lsm_pool_kernel<<<(NN * 32 + TB - 1) / TB, TB>>>(b2, batch);
    final_kernel<<<1, 64>>>(lin_W, lin_b, out);
}

// round 3
// speedup vs baseline: 1.2607x; 1.2607x over previous
#include <cuda_runtime.h>
#include <math.h>

#define NN 50000
#define EE 800000
#define ET (EE + NN)
#define GG 64
#define F_IN 128
#define H1DIM 256   // HEADS * HID
#define H2DIM 32
#define NEG_SLOPE 0.2f

// ---------------- scratch (device globals) ----------------
__device__ __align__(16) float g_h1[NN * H1DIM];
__device__ __align__(16) float g_out1[NN * H1DIM];
__device__ __align__(16) float g_as1[NN * 4];
__device__ __align__(16) float g_ad1[NN * 4];
__device__ __align__(16) float g_m1[NN * 4];
__device__ __align__(16) float g_den1[NN * 4];
__device__ __align__(16) float g_ex1[ET * 4];
__device__ __align__(16) float g_h2[NN * H2DIM];
__device__ float g_as2[NN];
__device__ float g_ad2[NN];
__device__ float g_m2[NN];
__device__ float g_den2[NN];
__device__ float g_ex2[ET];
__device__ float g_pool[GG * H2DIM];
__device__ float g_cnt[GG];
// CSR (sorted by dst), rebuilt each launch
__device__ int g_deg[NN];
__device__ int g_cur[NN];
__device__ int g_off[NN + 1];
__device__ int g_csr_eid[ET];
__device__ int g_csr_src[ET];

// ---------------- helpers ----------------
__device__ __forceinline__ void atomicMaxF(float* addr, float val) {
    int bits = __float_as_int(val);
    if (bits >= 0) atomicMax((int*)addr, bits);
    else           atomicMin((unsigned int*)addr, (unsigned int)bits);
}

__device__ __forceinline__ float leaky(float e) {
    return (e >= 0.f) ? e : NEG_SLOPE * e;
}

__device__ __forceinline__ void edge_src_dst(const int* adj, int e, int& src, int& dst) {
    if (e < EE) { src = adj[e]; dst = adj[EE + e]; }
    else        { src = dst = e - EE; }
}

__device__ __forceinline__ unsigned long long pack2(float a, float b) {
    unsigned long long r;
    asm("mov.b64 %0, {%1, %2};" : "=l"(r) : "f"(a), "f"(b));
    return r;
}
__device__ __forceinline__ void unpack2(unsigned long long v, float& a, float& b) {
    asm("mov.b64 {%0, %1}, %2;" : "=f"(a), "=f"(b) : "l"(v));
}
__device__ __forceinline__ void fma2(unsigned long long& acc, unsigned long long a, unsigned long long b) {
    asm("fma.rn.f32x2 %0, %1, %2, %0;" : "+l"(acc) : "l"(a), "l"(b));
}

// ---------------- init ----------------
__global__ void init_kernel() {
    int stride = gridDim.x * blockDim.x;
    int i0 = blockIdx.x * blockDim.x + threadIdx.x;
    for (int j = i0; j < NN; j += stride) { g_deg[j] = 0; g_cur[j] = 0; g_den2[j] = 0.f; g_m2[j] = -INFINITY; }
    for (int j = i0; j < NN * 4; j += stride) { g_den1[j] = 0.f; g_m1[j] = -INFINITY; }
    for (int j = i0; j < GG * H2DIM; j += stride) g_pool[j] = 0.f;
    for (int j = i0; j < GG; j += stride) g_cnt[j] = 0.f;
}

// ---------------- CSR build ----------------
__global__ void hist_kernel(const int* __restrict__ adj) {
    int e = blockIdx.x * blockDim.x + threadIdx.x;
    if (e >= ET) return;
    int dst = (e < EE) ? adj[EE + e] : e - EE;
    atomicAdd(&g_deg[dst], 1);
}

__global__ void scan_kernel() {
    __shared__ int part[1024];
    int tid = threadIdx.x;
    const int CH = (NN + 1023) / 1024;
    int start = tid * CH;
    int end = min(start + CH, NN);
    int s = 0;
    for (int i = start; i < end; i++) s += g_deg[i];
    part[tid] = s;
    __syncthreads();
    for (int off = 1; off < 1024; off <<= 1) {
        int v = (tid >= off) ? part[tid - off] : 0;
        __syncthreads();
        part[tid] += v;
        __syncthreads();
    }
    int base = (tid == 0) ? 0 : part[tid - 1];
    for (int i = start; i < end; i++) { g_off[i] = base; base += g_deg[i]; }
    if (tid == 1023) g_off[NN] = part[1023];
}

__global__ void scatter_kernel(const int* __restrict__ adj) {
    int e = blockIdx.x * blockDim.x + threadIdx.x;
    if (e >= ET) return;
    int src, dst; edge_src_dst(adj, e, src, dst);
    int slot = atomicAdd(&g_cur[dst], 1);
    int p = g_off[dst] + slot;
    g_csr_eid[p] = e;
    g_csr_src[p] = src;
}

// ---------------- GEMM1: h1 = x @ W1  (NNx128 @ 128x256), f32x2 packed ----------------
// block 256, 16 rows/block, thread = column
__global__ void gemm1_kernel(const float* __restrict__ x, const float* __restrict__ W1) {
    __shared__ float xs[16][F_IN];
    int row0 = blockIdx.x * 16;
    int tid = threadIdx.x;
    const float4* xsrc = (const float4*)(x + row0 * F_IN);
    float4* xdst = (float4*)&xs[0][0];
#pragma unroll
    for (int i = tid; i < 16 * F_IN / 4; i += 256) xdst[i] = xsrc[i];
    __syncthreads();
    int col = tid;
    unsigned long long acc[16];
#pragma unroll
    for (int r = 0; r < 16; r++) acc[r] = 0ull;
#pragma unroll 4
    for (int k = 0; k < F_IN; k += 2) {
        float w0 = W1[k * H1DIM + col];
        float w1 = W1[(k + 1) * H1DIM + col];
        unsigned long long wp = pack2(w0, w1);
#pragma unroll
        for (int r = 0; r < 16; r++) {
            unsigned long long xv = *(const unsigned long long*)&xs[r][k];
            fma2(acc[r], xv, wp);
        }
    }
#pragma unroll
    for (int r = 0; r < 16; r++) {
        float lo, hi; unpack2(acc[r], lo, hi);
        g_h1[(row0 + r) * H1DIM + col] = lo + hi;
    }
}

// ---------------- alpha1: per-node per-head dot products ----------------
__global__ void alpha1_kernel(const float* __restrict__ a_src, const float* __restrict__ a_dst) {
    int warp = (blockIdx.x * blockDim.x + threadIdx.x) >> 5;
    int lane = threadIdx.x & 31;
    if (warp >= NN) return;
    const float4* hrow = (const float4*)&g_h1[warp * H1DIM];
    float4 h0 = hrow[lane * 2], h1v = hrow[lane * 2 + 1];
    float4 s0 = ((const float4*)a_src)[lane * 2], s1 = ((const float4*)a_src)[lane * 2 + 1];
    float4 d0 = ((const float4*)a_dst)[lane * 2], d1 = ((const float4*)a_dst)[lane * 2 + 1];
    float ps = h0.x*s0.x + h0.y*s0.y + h0.z*s0.z + h0.w*s0.w
             + h1v.x*s1.x + h1v.y*s1.y + h1v.z*s1.z + h1v.w*s1.w;
    float pd = h0.x*d0.x + h0.y*d0.y + h0.z*d0.z + h0.w*d0.w
             + h1v.x*d1.x + h1v.y*d1.y + h1v.z*d1.z + h1v.w*d1.w;
#pragma unroll
    for (int off = 4; off; off >>= 1) {
        ps += __shfl_down_sync(0xffffffffu, ps, off);
        pd += __shfl_down_sync(0xffffffffu, pd, off);
    }
    if ((lane & 7) == 0) {
        g_as1[warp * 4 + (lane >> 3)] = ps;
        g_ad1[warp * 4 + (lane >> 3)] = pd;
    }
}

// ---------------- edge pass 1 (layer1): e + leaky + segment max ----------------
__global__ void edge1_max_kernel(const int* __restrict__ adj) {
    int e = blockIdx.x * blockDim.x + threadIdx.x;
    if (e >= ET) return;
    int src, dst; edge_src_dst(adj, e, src, dst);
    float4 as = *(const float4*)&g_as1[src * 4];
    float4 ad = *(const float4*)&g_ad1[dst * 4];
    float4 ev;
    ev.x = leaky(as.x + ad.x);
    ev.y = leaky(as.y + ad.y);
    ev.z = leaky(as.z + ad.z);
    ev.w = leaky(as.w + ad.w);
    *(float4*)&g_ex1[e * 4] = ev;
    atomicMaxF(&g_m1[dst * 4 + 0], ev.x);
    atomicMaxF(&g_m1[dst * 4 + 1], ev.y);
    atomicMaxF(&g_m1[dst * 4 + 2], ev.z);
    atomicMaxF(&g_m1[dst * 4 + 3], ev.w);
}

// ---------------- edge pass 2 (layer1): exp + segment sum (den) ----------------
__global__ void edge1_exp_kernel(const int* __restrict__ adj) {
    int e = blockIdx.x * blockDim.x + threadIdx.x;
    if (e >= ET) return;
    int dst = (e < EE) ? adj[EE + e] : e - EE;
    float4 ev = *(const float4*)&g_ex1[e * 4];
    float4 m = *(const float4*)&g_m1[dst * 4];
    float4 xv;
    xv.x = expf(ev.x - m.x);
    xv.y = expf(ev.y - m.y);
    xv.z = expf(ev.z - m.z);
    xv.w = expf(ev.w - m.w);
    *(float4*)&g_ex1[e * 4] = xv;
    asm volatile("red.global.add.v4.f32 [%0], {%1,%2,%3,%4};"
                 :: "l"(&g_den1[dst * 4]), "f"(xv.x), "f"(xv.y), "f"(xv.z), "f"(xv.w)
                 : "memory");
}

// ---------------- agg1 (CSR): out1[n] = relu((sum_e ex*h1[src])/den + b1) ----------------
// 64 threads per node (one float4 chunk each)
__global__ void agg1_kernel(const float* __restrict__ b1) {
    int gt = blockIdx.x * blockDim.x + threadIdx.x;
    int n = gt >> 6;
    if (n >= NN) return;
    int c = gt & 63;
    int head = c >> 4;
    float4 acc = make_float4(0.f, 0.f, 0.f, 0.f);
    int beg = g_off[n], end = g_off[n + 1];
    for (int i = beg; i < end; i++) {
        int eid = g_csr_eid[i];
        int src = g_csr_src[i];
        float a = g_ex1[eid * 4 + head];
        float4 hv = *(const float4*)&g_h1[src * H1DIM + c * 4];
        acc.x = fmaf(a, hv.x, acc.x);
        acc.y = fmaf(a, hv.y, acc.y);
        acc.z = fmaf(a, hv.z, acc.z);
        acc.w = fmaf(a, hv.w, acc.w);
    }
    float inv = 1.0f / g_den1[n * 4 + head];
    float4 b = ((const float4*)b1)[c];
    float4 o;
    o.x = fmaxf(fmaf(acc.x, inv, b.x), 0.f);
    o.y = fmaxf(fmaf(acc.y, inv, b.y), 0.f);
    o.z = fmaxf(fmaf(acc.z, inv, b.z), 0.f);
    o.w = fmaxf(fmaf(acc.w, inv, b.w), 0.f);
    *(float4*)&g_out1[n * H1DIM + c * 4] = o;
}

// ---------------- GEMM2: h2 = out1 @ W2  (NNx256 @ 256x32), f32x2 packed ----------------
__global__ void gemm2_kernel(const float* __restrict__ W2) {
    __shared__ float xs[8][H1DIM];
    int row0 = blockIdx.x * 8;
    int tid = threadIdx.x;
    const float4* xsrc = (const float4*)&g_out1[row0 * H1DIM];
    float4* xdst = (float4*)&xs[0][0];
#pragma unroll
    for (int i = tid; i < 8 * H1DIM / 4; i += 256) xdst[i] = xsrc[i];
    __syncthreads();
    int r = tid >> 5, c = tid & 31;
    unsigned long long acc = 0ull;
#pragma unroll 8
    for (int k = 0; k < H1DIM; k += 2) {
        float w0 = W2[k * H2DIM + c];
        float w1 = W2[(k + 1) * H2DIM + c];
        unsigned long long wp = pack2(w0, w1);
        unsigned long long xv = *(const unsigned long long*)&xs[r][k];
        fma2(acc, xv, wp);
    }
    float lo, hi; unpack2(acc, lo, hi);
    g_h2[(row0 + r) * H2DIM + c] = lo + hi;
}

// ---------------- alpha2 ----------------
__global__ void alpha2_kernel(const float* __restrict__ a_src, const float* __restrict__ a_dst) {
    int warp = (blockIdx.x * blockDim.x + threadIdx.x) >> 5;
    int lane = threadIdx.x & 31;
    if (warp >= NN) return;
    float h = g_h2[warp * H2DIM + lane];
    float ps = h * a_src[lane];
    float pd = h * a_dst[lane];
#pragma unroll
    for (int off = 16; off; off >>= 1) {
        ps += __shfl_down_sync(0xffffffffu, ps, off);
        pd += __shfl_down_sync(0xffffffffu, pd, off);
    }
    if (lane == 0) { g_as2[warp] = ps; g_ad2[warp] = pd; }
}

// ---------------- edge passes (layer2) ----------------
__global__ void edge2_max_kernel(const int* __restrict__ adj) {
    int e = blockIdx.x * blockDim.x + threadIdx.x;
    if (e >= ET) return;
    int src, dst; edge_src_dst(adj, e, src, dst);
    float ev = leaky(g_as2[src] + g_ad2[dst]);
    g_ex2[e] = ev;
    atomicMaxF(&g_m2[dst], ev);
}

__global__ void edge2_exp_kernel(const int* __restrict__ adj) {
    int e = blockIdx.x * blockDim.x + threadIdx.x;
    if (e >= ET) return;
    int dst = (e < EE) ? adj[EE + e] : e - EE;
    float xv = expf(g_ex2[e] - g_m2[dst]);
    g_ex2[e] = xv;
    atomicAdd(&g_den2[dst], xv);
}

// ---------------- agg2 + bias + log_softmax + pool (fused, warp per node) ----------------
__global__ void agg2_lsm_kernel(const float* __restrict__ b2, const int* __restrict__ batch) {
    int gt = blockIdx.x * blockDim.x + threadIdx.x;
    int n = gt >> 5;
    if (n >= NN) return;
    int lane = gt & 31;
    float acc = 0.f;
    int beg = g_off[n], end = g_off[n + 1];
    for (int i = beg; i < end; i++) {
        int eid = g_csr_eid[i];
        int src = g_csr_src[i];
        acc = fmaf(g_ex2[eid], g_h2[src * H2DIM + lane], acc);
    }
    float v = acc / g_den2[n] + b2[lane];
    float mx = v;
#pragma unroll
    for (int off = 16; off; off >>= 1) mx = fmaxf(mx, __shfl_xor_sync(0xffffffffu, mx, off));
    float ex = expf(v - mx);
    float s = ex;
#pragma unroll
    for (int off = 16; off; off >>= 1) s += __shfl_xor_sync(0xffffffffu, s, off);
    float lsm = v - mx - logf(s);
    int b = batch[n];
    atomicAdd(&g_pool[b * H2DIM + lane], lsm);
    if (lane == 0) atomicAdd(&g_cnt[b], 1.0f);
}

// ---------------- final ----------------
__global__ void final_kernel(const float* __restrict__ lin_W, const float* __restrict__ lin_b,
                             float* __restrict__ out) {
    int g = threadIdx.x;
    if (g >= GG) return;
    float inv = 1.0f / fmaxf(g_cnt[g], 1.0f);
    float acc = lin_b[0];
#pragma unroll
    for (int j = 0; j < H2DIM; j++) acc += g_pool[g * H2DIM + j] * inv * lin_W[j];
    out[g] = acc;
}

// ---------------- launcher ----------------
extern "C" void kernel_launch(void* const* d_in, const int* in_sizes, int n_in,
                              void* d_out, int out_size) {
    const float* x      = (const float*)d_in[0];
    const int*   adj    = (const int*)d_in[1];
    const int*   batch  = (const int*)d_in[2];
    const float* W1     = (const float*)d_in[3];
    const float* a1_src = (const float*)d_in[4];
    const float* a1_dst = (const float*)d_in[5];
    const float* b1     = (const float*)d_in[6];
    const float* W2     = (const float*)d_in[7];
    const float* a2_src = (const float*)d_in[8];
    const float* a2_dst = (const float*)d_in[9];
    const float* b2     = (const float*)d_in[10];
    const float* lin_W  = (const float*)d_in[11];
    const float* lin_b  = (const float*)d_in[12];
    float* out = (float*)d_out;

    const int TB = 256;
    int eb = (ET + TB - 1) / TB;

    init_kernel<<<512, TB>>>();
    hist_kernel<<<eb, TB>>>(adj);
    scan_kernel<<<1, 1024>>>();
    scatter_kernel<<<eb, TB>>>(adj);

    gemm1_kernel<<<NN / 16, TB>>>(x, W1);
    alpha1_kernel<<<(NN * 32 + TB - 1) / TB, TB>>>(a1_src, a1_dst);

    edge1_max_kernel<<<eb, TB>>>(adj);
    edge1_exp_kernel<<<eb, TB>>>(adj);
    agg1_kernel<<<(NN * 64 + TB - 1) / TB, TB>>>(b1);

    gemm2_kernel<<<NN / 8, TB>>>(W2);
    alpha2_kernel<<<(NN * 32 + TB - 1) / TB, TB>>>(a2_src, a2_dst);

    edge2_max_kernel<<<eb, TB>>>(adj);
    edge2_exp_kernel<<<eb, TB>>>(adj);
    agg2_lsm_kernel<<<(NN * 32 + TB - 1) / TB, TB>>>(b2, batch);

    final_kernel<<<1, 64>>>(lin_W, lin_b, out);
}